// round 5
// baseline (speedup 1.0000x reference)
#include <cuda_runtime.h>

#define NB 4
#define NQS 512
#define NKS 1024
#define DD 64

typedef unsigned long long ull;

#define ADD2(o,a,b)   asm("add.rn.f32x2 %0, %1, %2;" : "=l"(o) : "l"(a), "l"(b))
#define FMA2(o,a,b,c) asm("fma.rn.f32x2 %0, %1, %2, %3;" : "=l"(o) : "l"(a), "l"(b), "l"(c))
#define ABSM 0x7FFFFFFF7FFFFFFFULL

// smem layout (floats) for attn kernel
#define S_STRIDE 1032
#define S_OFF    0                       // 4*1032 = 4128 (logits; later aliased as RED)
#define PD_STRIDE 2056
#define PD_OFF   4128                    // 4*2056 = 8224 (duplicated P pairs)
#define QD_OFF   (PD_OFF + 8224)        // 12352: 64*8 negated+duplicated q
#define MP_OFF   (QD_OFF + 512)         // 12864: 8 max partials
#define SP_OFF   (MP_OFF + 8)           // 12872: 8 sum partials
#define SMEM_FLOATS (SP_OFF + 8)        // 12880 -> 51520 B

// Scratch: k transposed per batch (kT[b][d][j]); q row-major.
__device__ __align__(16) float g_kT[NB * DD * NKS];
__device__ __align__(16) float g_q [NB * NQS * DD];

// ---------------------------------------------------------------------------
// MLP kernel: 32 rows/block, 256 thr = 32 rows x 8 slices (8 outs each).
// Grid 192: [0,128) key path (4096 rows), [128,192) query path (2048 rows).
// Key-path output staged in smem and written TRANSPOSED but COALESCED.
// ---------------------------------------------------------------------------
__device__ __forceinline__ void mlp_layer(const float* __restrict__ in_row,
                                          const float* __restrict__ Ws, int sl,
                                          const float* __restrict__ bs,
                                          float4 acc[2])
{
    acc[0] = ((const float4*)bs)[sl * 2 + 0];
    acc[1] = ((const float4*)bs)[sl * 2 + 1];
#pragma unroll 8
    for (int din = 0; din < 64; din++) {
        float xv = in_row[din];
        const float4* wr = (const float4*)(Ws + din * 64) + sl * 2;
        float4 w0 = wr[0], w1 = wr[1];
        acc[0].x = fmaf(xv, w0.x, acc[0].x);
        acc[0].y = fmaf(xv, w0.y, acc[0].y);
        acc[0].z = fmaf(xv, w0.z, acc[0].z);
        acc[0].w = fmaf(xv, w0.w, acc[0].w);
        acc[1].x = fmaf(xv, w1.x, acc[1].x);
        acc[1].y = fmaf(xv, w1.y, acc[1].y);
        acc[1].z = fmaf(xv, w1.z, acc[1].z);
        acc[1].w = fmaf(xv, w1.w, acc[1].w);
    }
}

__global__ __launch_bounds__(256) void mlp_kernel(
    const float* __restrict__ x1, const float* __restrict__ x2,
    const float* __restrict__ Wk1, const float* __restrict__ bk1,
    const float* __restrict__ Wk2, const float* __restrict__ bk2,
    const float* __restrict__ Wq1, const float* __restrict__ bq1,
    const float* __restrict__ Wq2, const float* __restrict__ bq2)
{
    extern __shared__ float sm[];
    float* W1s = sm;             // 4096
    float* W2s = sm + 4096;      // 4096
    float* b1s = sm + 8192;      // 64
    float* b2s = sm + 8256;      // 64
    float* xs  = sm + 8320;      // 32*65 = 2080
    float* hs  = sm + 10400;     // 2080 (hidden; later reused for output staging)
    // total 12480 floats = 49920 B

    const int t = threadIdx.x;
    const bool keypath = blockIdx.x < 128;
    const float *x, *W1, *b1, *W2, *b2;
    int row0;
    if (keypath) { x = x1; W1 = Wk1; b1 = bk1; W2 = Wk2; b2 = bk2; row0 = blockIdx.x * 32; }
    else         { x = x2; W1 = Wq1; b1 = bq1; W2 = Wq2; b2 = bq2; row0 = (blockIdx.x - 128) * 32; }

    for (int idx = t; idx < 1024; idx += 256) {
        ((float4*)W1s)[idx] = ((const float4*)W1)[idx];
        ((float4*)W2s)[idx] = ((const float4*)W2)[idx];
    }
    if (t < 16) {
        ((float4*)b1s)[t] = ((const float4*)b1)[t];
        ((float4*)b2s)[t] = ((const float4*)b2)[t];
    }
#pragma unroll
    for (int u = t; u < 512; u += 256) {
        int rr = u >> 4, c = u & 15;
        float4 v = ((const float4*)(x + (size_t)(row0 + rr) * DD))[c];
        xs[rr * 65 + c * 4 + 0] = v.x;
        xs[rr * 65 + c * 4 + 1] = v.y;
        xs[rr * 65 + c * 4 + 2] = v.z;
        xs[rr * 65 + c * 4 + 3] = v.w;
    }
    __syncthreads();

    const int row = t >> 3, sl = t & 7;

    float4 acc[2];
    mlp_layer(xs + row * 65, W1s, sl, b1s, acc);   // layer 1
    {
        float* h = hs + row * 65 + sl * 8;
        h[0] = fmaxf(acc[0].x, 0.f); h[1] = fmaxf(acc[0].y, 0.f);
        h[2] = fmaxf(acc[0].z, 0.f); h[3] = fmaxf(acc[0].w, 0.f);
        h[4] = fmaxf(acc[1].x, 0.f); h[5] = fmaxf(acc[1].y, 0.f);
        h[6] = fmaxf(acc[1].z, 0.f); h[7] = fmaxf(acc[1].w, 0.f);
    }
    __syncthreads();
    mlp_layer(hs + row * 65, W2s, sl, b2s, acc);   // layer 2 (no relu)

    if (keypath) {
        // stage output in xs (reuse; x no longer needed): xs[row][d], stride 65
        __syncthreads();
        {
            float* o = xs + row * 65 + sl * 8;
            o[0] = acc[0].x; o[1] = acc[0].y; o[2] = acc[0].z; o[3] = acc[0].w;
            o[4] = acc[1].x; o[5] = acc[1].y; o[6] = acc[1].z; o[7] = acc[1].w;
        }
        __syncthreads();
        // transposed coalesced store: g_kT[b][d][j0 + j], warp covers 32 j's
        const int b  = row0 >> 10;
        const int j0 = row0 & 1023;
        float* o = g_kT + (size_t)b * DD * NKS + j0;
#pragma unroll
        for (int u = 0; u < 8; u++) {
            int idx = u * 256 + t;
            int d = idx >> 5, j = idx & 31;
            o[(size_t)d * NKS + j] = xs[j * 65 + d];
        }
    } else {
        const int rg = row0 + row;
        float4* o = (float4*)(g_q + (size_t)rg * DD) + sl * 2;
        o[0] = acc[0]; o[1] = acc[1];
    }
}

// ---------------------------------------------------------------------------
// Attention: one block = (b, 4 queries), 256 thr, grid (128,4) = 512 CTAs.
// Phase 1: packed f32x2 logits, 4q x 2 key-pairs/thread (2 indep LDG chains).
// Phase 2: softmax on 8 warps (2 per row), two-pass via smem partials.
// Phase 3: FFMA2 P@r, r direct from L2, 8-way K-split + smem reduction.
// ---------------------------------------------------------------------------
__global__ __launch_bounds__(256, 3) void attn_kernel(
    const float* __restrict__ rv, float* __restrict__ out)
{
    extern __shared__ float sm[];
    float* S    = sm + S_OFF;      // [4][1032] logits (aliased later as RED)
    float* PD   = sm + PD_OFF;     // [4][2056] duplicated P pairs
    float* QD   = sm + QD_OFF;     // [64][8] (-q) duplicated pairs
    float* Mp   = sm + MP_OFF;     // [4][2] max partials
    float* Sp   = sm + SP_OFF;     // [4][2] sum partials

    const int b    = blockIdx.y;
    const int qt   = blockIdx.x;
    const int t    = threadIdx.x;
    const int lane = t & 31;
    const int w    = t >> 5;

    // stage QD[d][2i..2i+1] = -q[i][d] (negated + duplicated)
    {
        const int d = t >> 2, i = t & 3;
        float v = g_q[(size_t)(b * NQS + qt * 4 + i) * DD + d];
        QD[d * 8 + 2 * i + 0] = -v;
        QD[d * 8 + 2 * i + 1] = -v;
    }
    __syncthreads();

    const float* kTg = g_kT + (size_t)b * DD * NKS;

    // -------- Phase 1: logits, 2 independent key-pair chains per thread ----
    {
        const int j0 = w * 64 + 2 * lane;   // keys [w*64, w*64+64)
        const int j1 = 512 + j0;            // keys [512+w*64, ...)
        const float* kp0 = kTg + j0;
        const float* kp1 = kTg + j1;

        ull a00 = 0, a01 = 0, a02 = 0, a03 = 0;   // chain A: 4 queries
        ull a10 = 0, a11 = 0, a12 = 0, a13 = 0;   // chain B: 4 queries
#pragma unroll 8
        for (int d = 0; d < 64; d++) {
            ull kA = *(const ull*)(kp0 + (size_t)d * NKS);
            ull kB = *(const ull*)(kp1 + (size_t)d * NKS);
            ulonglong2 nq01 = *(const ulonglong2*)(QD + d * 8);
            ulonglong2 nq23 = *(const ulonglong2*)(QD + d * 8 + 4);
            ull u;
            ADD2(u, kA, nq01.x); u &= ABSM; ADD2(a00, a00, u);
            ADD2(u, kA, nq01.y); u &= ABSM; ADD2(a01, a01, u);
            ADD2(u, kA, nq23.x); u &= ABSM; ADD2(a02, a02, u);
            ADD2(u, kA, nq23.y); u &= ABSM; ADD2(a03, a03, u);
            ADD2(u, kB, nq01.x); u &= ABSM; ADD2(a10, a10, u);
            ADD2(u, kB, nq01.y); u &= ABSM; ADD2(a11, a11, u);
            ADD2(u, kB, nq23.x); u &= ABSM; ADD2(a12, a12, u);
            ADD2(u, kB, nq23.y); u &= ABSM; ADD2(a13, a13, u);
        }
        const ull accA[4] = {a00, a01, a02, a03};
        const ull accB[4] = {a10, a11, a12, a13};
#pragma unroll
        for (int q = 0; q < 4; q++) {
            ull a = accA[q], bq = accB[q];
            *(float2*)(S + q * S_STRIDE + j0) =
                make_float2(-__uint_as_float((unsigned)a),
                            -__uint_as_float((unsigned)(a >> 32)));
            *(float2*)(S + q * S_STRIDE + j1) =
                make_float2(-__uint_as_float((unsigned)bq),
                            -__uint_as_float((unsigned)(bq >> 32)));
        }
    }
    __syncthreads();

    // -------- Phase 2: softmax, 2 warps per row (halves of 1024 keys) ------
    {
        const int row  = w >> 1;
        const int half = w & 1;
        const float* Srow = S + row * S_STRIDE + half * 512;
        float* Prow = PD + row * PD_STRIDE + half * 1024;

        float m = -3.0e38f;
#pragma unroll
        for (int it = 0; it < 16; it++) m = fmaxf(m, Srow[it * 32 + lane]);
#pragma unroll
        for (int o = 16; o; o >>= 1) m = fmaxf(m, __shfl_xor_sync(0xffffffffu, m, o));
        if (lane == 0) Mp[row * 2 + half] = m;
        __syncthreads();
        const float M = fmaxf(Mp[row * 2], Mp[row * 2 + 1]);

        float sum = 0.f;
#pragma unroll
        for (int it = 0; it < 16; it++) {
            float p = __expf(Srow[it * 32 + lane] - M);
            *(float2*)(Prow + 2 * (it * 32 + lane)) = make_float2(p, p);
            sum += p;
        }
#pragma unroll
        for (int o = 16; o; o >>= 1) sum += __shfl_xor_sync(0xffffffffu, sum, o);
        if (lane == 0) Sp[row * 2 + half] = sum;
    }
    __syncthreads();

    // -------- Phase 3: O = P @ r via FFMA2, 8-way K split ------------------
    const int kg = t >> 5;          // warp = K group (128 keys each)
    const int qg = (t >> 4) & 1;    // query pair
    const int dg = t & 15;          // float4 of output dims
    const float* rb  = rv + (size_t)b * NKS * DD + (size_t)kg * 128 * DD + dg * 4;
    const float* PD0 = PD + (qg * 2 + 0) * PD_STRIDE + kg * 256;
    const float* PD1 = PD + (qg * 2 + 1) * PD_STRIDE + kg * 256;

    ull aA0 = 0, aA1 = 0, aB0 = 0, aB1 = 0;
#pragma unroll 8
    for (int kk = 0; kk < 128; kk++) {
        ull p0 = *(const ull*)(PD0 + 2 * kk);
        ull p1 = *(const ull*)(PD1 + 2 * kk);
        ulonglong2 r2 = *(const ulonglong2*)(rb + (size_t)kk * DD);
        FMA2(aA0, p0, r2.x, aA0);
        FMA2(aA1, p0, r2.y, aA1);
        FMA2(aB0, p1, r2.x, aB0);
        FMA2(aB1, p1, r2.y, aB1);
    }

    // partials -> RED (aliases S region; S dead after phase 2)
    float4* RED = (float4*)sm;
    {
        float4 vA = make_float4(__uint_as_float((unsigned)aA0),
                                __uint_as_float((unsigned)(aA0 >> 32)),
                                __uint_as_float((unsigned)aA1),
                                __uint_as_float((unsigned)(aA1 >> 32)));
        float4 vB = make_float4(__uint_as_float((unsigned)aB0),
                                __uint_as_float((unsigned)(aB0 >> 32)),
                                __uint_as_float((unsigned)aB1),
                                __uint_as_float((unsigned)(aB1 >> 32)));
        RED[kg * 64 + (qg * 2 + 0) * 16 + dg] = vA;
        RED[kg * 64 + (qg * 2 + 1) * 16 + dg] = vB;
    }
    __syncthreads();

    if (t < 64) {
        const int q = t >> 4, dd = t & 15;
        float4 s = RED[q * 16 + dd];
#pragma unroll
        for (int g = 1; g < 8; g++) {
            float4 v = RED[g * 64 + q * 16 + dd];
            s.x += v.x; s.y += v.y; s.z += v.z; s.w += v.w;
        }
        const float li = 1.0f / (Sp[q * 2] + Sp[q * 2 + 1]);
        s.x *= li; s.y *= li; s.z *= li; s.w *= li;
        ((float4*)(out + (size_t)(b * NQS + qt * 4 + q) * DD))[dd] = s;
    }
}

// ---------------------------------------------------------------------------
extern "C" void kernel_launch(void* const* d_in, const int* in_sizes, int n_in,
                              void* d_out, int out_size)
{
    const float* x1  = (const float*)d_in[0];
    const float* x2  = (const float*)d_in[1];
    const float* r   = (const float*)d_in[2];
    const float* Wk1 = (const float*)d_in[3];
    const float* bk1 = (const float*)d_in[4];
    const float* Wk2 = (const float*)d_in[5];
    const float* bk2 = (const float*)d_in[6];
    const float* Wq1 = (const float*)d_in[7];
    const float* bq1 = (const float*)d_in[8];
    const float* Wq2 = (const float*)d_in[9];
    const float* bq2 = (const float*)d_in[10];
    float* out = (float*)d_out;

    cudaFuncSetAttribute(mlp_kernel,  cudaFuncAttributeMaxDynamicSharedMemorySize, 49920);
    cudaFuncSetAttribute(attn_kernel, cudaFuncAttributeMaxDynamicSharedMemorySize, SMEM_FLOATS * 4);

    mlp_kernel<<<192, 256, 49920>>>(x1, x2, Wk1, bk1, Wk2, bk2, Wq1, bq1, Wq2, bq2);
    attn_kernel<<<dim3(128, 4), 256, SMEM_FLOATS * 4>>>(r, out);
}